// round 17
// baseline (speedup 1.0000x reference)
// v16r: identical to round-16 submission (broker infra failure; re-audited OK).
#include <cuda_runtime.h>
#include <cuda_fp16.h>
#include <stdint.h>
#include <math.h>

#define L_    2048
#define NB    2
#define E_    2048
#define I_    2048
#define H_    16
#define DH    128
#define ROWS  (L_*NB)        // 4096
#define WELEM (I_*E_)        // 4194304

__device__ __half g_A16[(size_t)ROWS * I_];     // GEMM A input (query, then ctx)
__device__ __half g_W16[(size_t)4 * WELEM];     // weights fp16 (contiguous)
__device__ __half g_Q16[(size_t)ROWS * I_];
__device__ __half g_K16[(size_t)ROWS * I_];
__device__ __half g_V16[(size_t)ROWS * I_];

// ---------------------------------------------------------------------------
static __device__ __forceinline__ uint32_t smem_u32(const void* p) {
    uint32_t a;
    asm("{ .reg .u64 t; cvta.to.shared.u64 t, %1; cvt.u32.u64 %0, t; }"
        : "=r"(a) : "l"(p));
    return a;
}
static __device__ __forceinline__ void cp_async16(uint32_t dst, const void* src) {
    asm volatile("cp.async.cg.shared.global [%0], [%1], 16;" :: "r"(dst), "l"(src));
}
static __device__ __forceinline__ void cp_commit() {
    asm volatile("cp.async.commit_group;");
}
static __device__ __forceinline__ void cp_wait1() {
    asm volatile("cp.async.wait_group 1;" ::: "memory");
}
static __device__ __forceinline__ void cp_wait0() {
    asm volatile("cp.async.wait_group 0;" ::: "memory");
}
static __device__ __forceinline__ void ldm_x4(uint32_t& r0, uint32_t& r1,
                                              uint32_t& r2, uint32_t& r3, uint32_t a) {
    asm volatile("ldmatrix.sync.aligned.m8n8.x4.shared.b16 {%0,%1,%2,%3}, [%4];"
                 : "=r"(r0), "=r"(r1), "=r"(r2), "=r"(r3) : "r"(a));
}
static __device__ __forceinline__ void ldm_x4_t(uint32_t& r0, uint32_t& r1,
                                                uint32_t& r2, uint32_t& r3, uint32_t a) {
    asm volatile("ldmatrix.sync.aligned.m8n8.x4.trans.shared.b16 {%0,%1,%2,%3}, [%4];"
                 : "=r"(r0), "=r"(r1), "=r"(r2), "=r"(r3) : "r"(a));
}
static __device__ __forceinline__ void mma_f16(float* d, const uint32_t* a,
                                               const uint32_t* b) {
    asm volatile(
        "mma.sync.aligned.m16n8k16.row.col.f32.f16.f16.f32 "
        "{%0,%1,%2,%3}, {%4,%5,%6,%7}, {%8,%9}, {%0,%1,%2,%3};"
        : "+f"(d[0]), "+f"(d[1]), "+f"(d[2]), "+f"(d[3])
        : "r"(a[0]), "r"(a[1]), "r"(a[2]), "r"(a[3]), "r"(b[0]), "r"(b[1]));
}
static __device__ __forceinline__ uint32_t packh(float x, float y) {
    __half2 t = __floats2half2_rn(x, y);
    return *reinterpret_cast<uint32_t*>(&t);
}

// ---------------------------------------------------------------------------
// Fused fp32 -> fp16 cast over [query | qw | kw | vw | ow].
// ---------------------------------------------------------------------------
__global__ __launch_bounds__(256) void cast_all(
    const float* __restrict__ query, const float* __restrict__ qw,
    const float* __restrict__ kw, const float* __restrict__ vw,
    const float* __restrict__ ow)
{
    const int i = blockIdx.x * blockDim.x + threadIdx.x;
    const size_t e = (size_t)4 * i;
    const size_t nA = (size_t)ROWS * I_;
    const float* src;
    __half* dst;
    if (e < nA) {
        src = query + e;
        dst = g_A16 + e;
    } else {
        size_t r = e - nA;
        dst = g_W16 + r;
        int w = (int)(r >> 22);
        size_t off = r & (WELEM - 1);
        src = ((w == 0) ? qw : (w == 1) ? kw : (w == 2) ? vw : ow) + off;
    }
    float4 v = *(const float4*)src;
    ((uint32_t*)dst)[0] = packh(v.x, v.y);
    ((uint32_t*)dst)[1] = packh(v.z, v.w);
}

// ---------------------------------------------------------------------------
// fp16 GEMM core: tile 128x128, BK=32, 3-stage single-barrier pipeline.
// Loader collapsed to 1 smem offset + 2 gmem pointers (immediate adds);
// __launch_bounds__(256,3) targets 3 CTAs/SM.
// ---------------------------------------------------------------------------
#define GTIL 8192
#define GSTG 16384

template<bool QKV>
__global__ __launch_bounds__(256, 3) void gemm_f16(
    const float* __restrict__ b0, const float* __restrict__ b1,
    const float* __restrict__ b2, float* __restrict__ Copt, float scale)
{
    extern __shared__ __align__(16) char smem[];
    const uint32_t sbase = smem_u32(smem);

    const int tid  = threadIdx.x;
    const int wid  = tid >> 5;
    const int lane = tid & 31;
    const int wm = wid >> 2;
    const int wn = wid & 3;
    const int bm = blockIdx.y * 128;
    const int bn = blockIdx.x * 128;
    const int z  = QKV ? blockIdx.z : 3;

    const __half* Bw = g_W16 + (size_t)z * WELEM;
    const float* bias = QKV ? (z == 0 ? b0 : (z == 1 ? b1 : b2)) : b0;

    // Collapsed loader: thread covers rows {r, r+64} of both A and B at
    // k-chunk c. Swizzle invariant under +64 rows.
    const int lr4 = tid >> 2;          // 0..63
    const int lc4 = tid & 3;           // 0..3
    const uint32_t ub = (uint32_t)(lr4 * 64 + ((lc4 ^ ((lr4 >> 1) & 3)) << 4));
    const __half* pA = g_A16 + (size_t)(bm + lr4) * 2048 + lc4 * 8;
    const __half* pB = Bw   + (size_t)(bn + lr4) * 2048 + lc4 * 8;

    const int frow = lane & 15;
    const int fhal = lane >> 4;
    const int fsw  = (frow >> 1) & 3;
    const uint32_t cof0 = (uint32_t)(((0 + fhal) ^ fsw) * 16);
    const uint32_t cof1 = (uint32_t)(((2 + fhal) ^ fsw) * 16);

    float acc[4][4][4];
#pragma unroll
    for (int i = 0; i < 4; i++)
#pragma unroll
        for (int j = 0; j < 4; j++)
#pragma unroll
            for (int q = 0; q < 4; q++) acc[i][j][q] = 0.0f;

#pragma unroll
    for (int ps = 0; ps < 2; ps++) {
        const uint32_t stg = sbase + (uint32_t)(ps * GSTG) + ub;
        cp_async16(stg,               pA + ps * 32);
        cp_async16(stg + 4096,        pA + 64 * 2048 + ps * 32);
        cp_async16(stg + GTIL,        pB + ps * 32);
        cp_async16(stg + GTIL + 4096, pB + 64 * 2048 + ps * 32);
        cp_commit();
    }

    int cur = 0;
    for (int s = 0; s < 64; s++) {
        if (s < 63) cp_wait1(); else cp_wait0();
        __syncthreads();

        if (s + 2 < 64) {
            int nxt2 = cur + 2; if (nxt2 >= 3) nxt2 -= 3;
            const uint32_t stg = sbase + (uint32_t)(nxt2 * GSTG) + ub;
            cp_async16(stg,               pA + (s + 2) * 32);
            cp_async16(stg + 4096,        pA + 64 * 2048 + (s + 2) * 32);
            cp_async16(stg + GTIL,        pB + (s + 2) * 32);
            cp_async16(stg + GTIL + 4096, pB + 64 * 2048 + (s + 2) * 32);
            cp_commit();
        }

        const uint32_t stg = sbase + (uint32_t)(cur * GSTG);
        cur++; if (cur == 3) cur = 0;

#pragma unroll
        for (int ks = 0; ks < 2; ks++) {
            const uint32_t cof = ks ? cof1 : cof0;
            uint32_t bf[4][2];
#pragma unroll
            for (int pair = 0; pair < 2; pair++) {
                uint32_t r0, r1, r2, r3;
                ldm_x4(r0, r1, r2, r3,
                       stg + GTIL + (uint32_t)((wn * 32 + pair * 16 + frow) * 64) + cof);
                bf[2 * pair][0] = r0; bf[2 * pair][1] = r2;
                bf[2 * pair + 1][0] = r1; bf[2 * pair + 1][1] = r3;
            }
#pragma unroll
            for (int mf = 0; mf < 4; mf++) {
                uint32_t af[4];
                ldm_x4(af[0], af[1], af[2], af[3],
                       stg + (uint32_t)((wm * 64 + mf * 16 + frow) * 64) + cof);
#pragma unroll
                for (int nf = 0; nf < 4; nf++)
                    mma_f16(acc[mf][nf], af, bf[nf]);
            }
        }
    }

    if (!QKV) {
#pragma unroll
        for (int mf = 0; mf < 4; mf++) {
#pragma unroll
            for (int nf = 0; nf < 4; nf++) {
                const int row0 = bm + wm * 64 + mf * 16 + (lane >> 2);
                const int col  = bn + wn * 32 + nf * 8 + (lane & 3) * 2;
                float2 bv = *(const float2*)&bias[col];
                float2 o0, o1;
                o0.x = acc[mf][nf][0] + bv.x;
                o0.y = acc[mf][nf][1] + bv.y;
                o1.x = acc[mf][nf][2] + bv.x;
                o1.y = acc[mf][nf][3] + bv.y;
                *(float2*)&Copt[(size_t)row0 * 2048 + col] = o0;
                *(float2*)&Copt[(size_t)(row0 + 8) * 2048 + col] = o1;
            }
        }
    } else {
        const float alpha = (z == 0) ? scale : 1.0f;
        __half* dst = (z == 0) ? g_Q16 : (z == 1) ? g_K16 : g_V16;
#pragma unroll
        for (int mf = 0; mf < 4; mf++) {
#pragma unroll
            for (int nf = 0; nf < 4; nf++) {
                const int row0 = bm + wm * 64 + mf * 16 + (lane >> 2);
                const int col  = bn + wn * 32 + nf * 8 + (lane & 3) * 2;
                float2 bv = *(const float2*)&bias[col];
                *(uint32_t*)&dst[(size_t)row0 * 2048 + col] =
                    packh(alpha * (acc[mf][nf][0] + bv.x),
                          alpha * (acc[mf][nf][1] + bv.y));
                *(uint32_t*)&dst[(size_t)(row0 + 8) * 2048 + col] =
                    packh(alpha * (acc[mf][nf][2] + bv.x),
                          alpha * (acc[mf][nf][3] + bv.y));
            }
        }
    }
}

// ---------------------------------------------------------------------------
// fp16 HMMA causal flash attention (v15, unchanged): Bq=64, Bk=64, exp2
// softmax, rescale-skip, swizzled 48KB smem, heavy-first order.
// ---------------------------------------------------------------------------
#define QOFF 0
#define KOFF 16384
#define VOFF 32768
#define ATT_SMEM 49152
#define SWA(base, row, ch) ((base) + (uint32_t)((row) * 256 + (((ch) ^ ((row) & 7)) << 4)))

__global__ __launch_bounds__(128, 3) void flash_attn_f16()
{
    extern __shared__ __align__(16) char smem[];
    const uint32_t sb = smem_u32(smem);
    const int tid  = threadIdx.x;
    const int wid  = tid >> 5;
    const int lane = tid & 31;
    const int qt = gridDim.x - 1 - blockIdx.x;   // heavy-first
    const int bb = blockIdx.y;
    const int n  = bb / H_;
    const int h  = bb % H_;
    const int q0 = qt * 64;
    const int wr = q0 + wid * 16;
    const int colbase = h * DH;
    const int lr = lane >> 2;
    const int lc = lane & 3;
    const int frow = lane & 15;
    const int fhal = lane >> 4;

#pragma unroll
    for (int i = 0; i < 8; i++) {
        int c = tid + i * 128;
        int row = c >> 4;
        int ch  = c & 15;
        cp_async16(SWA(sb + QOFF, row, ch),
                   g_Q16 + ((size_t)(q0 + row) * NB + n) * 2048 + colbase + ch * 8);
    }
    cp_commit();

    float oacc[16][4];
#pragma unroll
    for (int f = 0; f < 16; f++)
#pragma unroll
        for (int q = 0; q < 4; q++) oacc[f][q] = 0.0f;
    float m_run[2] = {-1e30f, -1e30f};
    float l_run[2] = {0.0f, 0.0f};

    for (int jt = 0; jt <= qt; jt++) {
        const int k0 = jt * 64;
        __syncthreads();

#pragma unroll
        for (int i = 0; i < 8; i++) {
            int c = tid + i * 128;
            int row = c >> 4;
            int ch  = c & 15;
            cp_async16(SWA(sb + KOFF, row, ch),
                       g_K16 + ((size_t)(k0 + row) * NB + n) * 2048 + colbase + ch * 8);
        }
        cp_commit();
#pragma unroll
        for (int i = 0; i < 8; i++) {
            int c = tid + i * 128;
            int row = c >> 4;
            int ch  = c & 15;
            cp_async16(SWA(sb + VOFF, row, ch),
                       g_V16 + ((size_t)(k0 + row) * NB + n) * 2048 + colbase + ch * 8);
        }
        cp_commit();

        cp_wait1();
        __syncthreads();

        const bool active = (k0 <= wr + 15);
        uint32_t ph[4][4];

        if (active) {
            float sacc[8][4];
#pragma unroll
            for (int j = 0; j < 8; j++)
#pragma unroll
                for (int q = 0; q < 4; q++) sacc[j][q] = 0.0f;

#pragma unroll
            for (int t = 0; t < 8; t++) {
                uint32_t af[4];
                {
                    int row = wid * 16 + frow;
                    ldm_x4(af[0], af[1], af[2], af[3], SWA(sb + QOFF, row, 2 * t + fhal));
                }
#pragma unroll
                for (int g = 0; g < 4; g++) {
                    int row = (lane & 7) + ((lane >> 4) << 3) + 16 * g;
                    int ch  = 2 * t + ((lane >> 3) & 1);
                    uint32_t r0, r1, r2, r3;
                    ldm_x4(r0, r1, r2, r3, SWA(sb + KOFF, row, ch));
                    uint32_t k0f[2] = {r0, r1}, k1f[2] = {r2, r3};
                    mma_f16(sacc[2 * g],     af, k0f);
                    mma_f16(sacc[2 * g + 1], af, k1f);
                }
            }

            if (k0 + 63 > wr) {
                const int r0a = wr + lr, r1a = r0a + 8;
#pragma unroll
                for (int j = 0; j < 8; j++) {
                    int kc = k0 + 8 * j + 2 * lc;
                    if (kc > r0a)     sacc[j][0] = -1e30f;
                    if (kc + 1 > r0a) sacc[j][1] = -1e30f;
                    if (kc > r1a)     sacc[j][2] = -1e30f;
                    if (kc + 1 > r1a) sacc[j][3] = -1e30f;
                }
            }

#pragma unroll
            for (int r = 0; r < 2; r++) {
                float mt = -1e30f;
#pragma unroll
                for (int j = 0; j < 8; j++)
                    mt = fmaxf(mt, fmaxf(sacc[j][2 * r], sacc[j][2 * r + 1]));
                mt = fmaxf(mt, __shfl_xor_sync(0xffffffffu, mt, 1));
                mt = fmaxf(mt, __shfl_xor_sync(0xffffffffu, mt, 2));
                const float mold = m_run[r];
                const float mnew = fmaxf(mold, mt);
                m_run[r] = mnew;
                float rs = 0.0f;
#pragma unroll
                for (int j = 0; j < 8; j++) {
                    sacc[j][2 * r]     = exp2f(sacc[j][2 * r] - mnew);
                    sacc[j][2 * r + 1] = exp2f(sacc[j][2 * r + 1] - mnew);
                    rs += sacc[j][2 * r] + sacc[j][2 * r + 1];
                }
                rs += __shfl_xor_sync(0xffffffffu, rs, 1);
                rs += __shfl_xor_sync(0xffffffffu, rs, 2);
                if (mnew > mold) {
                    const float corr = exp2f(mold - mnew);
                    l_run[r] = l_run[r] * corr + rs;
#pragma unroll
                    for (int f = 0; f < 16; f++) {
                        oacc[f][2 * r]     *= corr;
                        oacc[f][2 * r + 1] *= corr;
                    }
                } else {
                    l_run[r] += rs;
                }
            }

#pragma unroll
            for (int t2 = 0; t2 < 4; t2++) {
                const float* s0 = sacc[2 * t2];
                const float* s1 = sacc[2 * t2 + 1];
                ph[t2][0] = packh(s0[0], s0[1]);
                ph[t2][1] = packh(s0[2], s0[3]);
                ph[t2][2] = packh(s1[0], s1[1]);
                ph[t2][3] = packh(s1[2], s1[3]);
            }
        }

        cp_wait0();
        __syncthreads();

        if (active) {
#pragma unroll
            for (int t2 = 0; t2 < 4; t2++) {
                int row = (lane & 7) + (((lane >> 3) & 1) << 3) + 16 * t2;
#pragma unroll
                for (int g = 0; g < 8; g++) {
                    int ch = 2 * g + (lane >> 4);
                    uint32_t r0, r1, r2, r3;
                    ldm_x4_t(r0, r1, r2, r3, SWA(sb + VOFF, row, ch));
                    uint32_t v0[2] = {r0, r1}, v1[2] = {r2, r3};
                    mma_f16(oacc[2 * g],     ph[t2], v0);
                    mma_f16(oacc[2 * g + 1], ph[t2], v1);
                }
            }
        }
    }

    const float inv0 = 1.0f / l_run[0];
    const float inv1 = 1.0f / l_run[1];
    const size_t base0 = ((size_t)(wr + lr) * NB + n) * 2048 + colbase;
    const size_t base1 = ((size_t)(wr + lr + 8) * NB + n) * 2048 + colbase;
#pragma unroll
    for (int f = 0; f < 16; f++) {
        const int c = 8 * f + 2 * lc;
        *(uint32_t*)&g_A16[base0 + c] = packh(oacc[f][0] * inv0, oacc[f][1] * inv0);
        *(uint32_t*)&g_A16[base1 + c] = packh(oacc[f][2] * inv1, oacc[f][3] * inv1);
    }
}

// ---------------------------------------------------------------------------
extern "C" void kernel_launch(void* const* d_in, const int* in_sizes, int n_in,
                              void* d_out, int out_size)
{
    (void)in_sizes; (void)n_in; (void)out_size;
    const float* query = (const float*)d_in[0];
    const float* qw    = (const float*)d_in[1];
    const float* qb    = (const float*)d_in[2];
    const float* kw    = (const float*)d_in[3];
    const float* kb    = (const float*)d_in[4];
    const float* vw    = (const float*)d_in[5];
    const float* vb    = (const float*)d_in[6];
    const float* ow    = (const float*)d_in[7];
    const float* ob    = (const float*)d_in[8];
    float* out = (float*)d_out;

    // 1/sqrt(128) * log2(e): softmax runs in base 2.
    const float scale_l2e = (float)(0.08838834764831845 * 1.4426950408889634);

    const int totalThreads = (ROWS * I_ + 4 * WELEM) / 4;
    cast_all<<<totalThreads / 256, 256>>>(query, qw, kw, vw, ow);

    gemm_f16<true><<<dim3(16, 32, 3), 256, 3 * GSTG>>>(qb, kb, vb, nullptr, scale_l2e);

    flash_attn_f16<<<dim3(L_ / 64, NB * H_), 128, ATT_SMEM>>>();

    gemm_f16<false><<<dim3(16, 32, 1), 256, 3 * GSTG>>>(ob, nullptr, nullptr, out, 1.0f);
}